// round 1
// baseline (speedup 1.0000x reference)
#include <cuda_runtime.h>
#include <math.h>

#define NMAX 150016
#define EMAX 3200000

// ---------------- static device scratch (no allocations allowed) ----------------
__device__ float  g_deg[NMAX];
__device__ float  g_dinv[NMAX];
__device__ int    g_cnt[NMAX];
__device__ int    g_cnt2[NMAX];
__device__ int    g_rs[NMAX + 2];
__device__ int    g_bsum[1024];
__device__ int2   g_csr[EMAX];          // {src, norm-as-bits}
__device__ float4 g_hw[NMAX * 16];      // h @ W scratch (row = 16 float4)
__device__ float4 g_h [NMAX * 16];      // node features (ping)
__device__ float4 g_h2[NMAX * 16];      // node features (pong)

// ---------------- helpers ----------------
__device__ __forceinline__ void fma4(float4& a, float s, const float4& w) {
    a.x += s * w.x; a.y += s * w.y; a.z += s * w.z; a.w += s * w.w;
}

// ---------------- concat x = [U; I] ----------------
__global__ void k_concat(const float4* __restrict__ U, const float4* __restrict__ I,
                         int nu16, int tot16) {
    for (int i = blockIdx.x * blockDim.x + threadIdx.x; i < tot16; i += gridDim.x * blockDim.x)
        g_h[i] = (i < nu16) ? U[i] : I[i - nu16];
}

// ---------------- init deg=1 (self loop), counters=0 ----------------
__global__ void k_init(int N) {
    int i = blockIdx.x * blockDim.x + threadIdx.x;
    if (i < N) { g_deg[i] = 1.0f; g_cnt[i] = 0; g_cnt2[i] = 0; }
}

// ---------------- degree + per-dst edge counts ----------------
__global__ void k_deg(const int* __restrict__ dst, const float* __restrict__ ew, int E) {
    for (int e = blockIdx.x * blockDim.x + threadIdx.x; e < E; e += gridDim.x * blockDim.x) {
        int d = dst[e];
        atomicAdd(&g_deg[d], ew[e]);
        atomicAdd(&g_cnt[d], 1);
    }
}

__global__ void k_dinv(int N) {
    int i = blockIdx.x * blockDim.x + threadIdx.x;
    if (i < N) g_dinv[i] = rsqrtf(g_deg[i]);   // deg >= 1 always (self loop)
}

// ---------------- exclusive scan of g_cnt -> g_rs (3-phase) ----------------
__global__ void k_scan1(int N) {
    __shared__ int sm[1024];
    int t = threadIdx.x;
    int i = blockIdx.x * 1024 + t;
    int x = (i < N) ? g_cnt[i] : 0;
    sm[t] = x;
    __syncthreads();
    for (int o = 1; o < 1024; o <<= 1) {
        int v = (t >= o) ? sm[t - o] : 0;
        __syncthreads();
        sm[t] += v;
        __syncthreads();
    }
    if (i < N) g_rs[i] = sm[t] - x;            // exclusive within block
    if (t == 1023) g_bsum[blockIdx.x] = sm[1023];
}

__global__ void k_scan2(int nb) {
    __shared__ int sm[1024];
    int t = threadIdx.x;
    int x = (t < nb) ? g_bsum[t] : 0;
    sm[t] = x;
    __syncthreads();
    for (int o = 1; o < 1024; o <<= 1) {
        int v = (t >= o) ? sm[t - o] : 0;
        __syncthreads();
        sm[t] += v;
        __syncthreads();
    }
    if (t < nb) g_bsum[t] = sm[t] - x;         // exclusive block offsets
}

__global__ void k_scan3(int N, int E) {
    int i = blockIdx.x * 1024 + threadIdx.x;
    if (i < N) g_rs[i] += g_bsum[blockIdx.x];
    if (i == 0) g_rs[N] = E;
}

// ---------------- CSR fill: bucket edges by dst, precompute norm ----------------
__global__ void k_fill(const int* __restrict__ src, const int* __restrict__ dst,
                       const float* __restrict__ ew, int E) {
    for (int e = blockIdx.x * blockDim.x + threadIdx.x; e < E; e += gridDim.x * blockDim.x) {
        int s = src[e], d = dst[e];
        float nrm = g_dinv[s] * ew[e] * g_dinv[d];
        int p = g_rs[d] + atomicAdd(&g_cnt2[d], 1);
        g_csr[p] = make_int2(s, __float_as_int(nrm));
    }
}

// ---------------- GEMM: Y[nrows,64] = X[nrows,64] @ W[64,64] (+bias) ----------------
__global__ __launch_bounds__(256) void k_gemm(const float4* __restrict__ X,
                                              const float* __restrict__ W,
                                              const float* __restrict__ bias,
                                              float4* __restrict__ Y, int nrows) {
    __shared__ __align__(16) float Xs[64][68];
    __shared__ __align__(16) float Ws[64][64];
    int t = threadIdx.x;
    int row0 = blockIdx.x * 64;

    const float4* W4 = (const float4*)W;
    for (int i = t; i < 1024; i += 256) {
        float4 v = W4[i];
        int k = i >> 4, c = (i & 15) << 2;
        *(float4*)&Ws[k][c] = v;
    }
    for (int i = t; i < 1024; i += 256) {
        int r = i >> 4, c4 = i & 15;
        float4 v = make_float4(0.f, 0.f, 0.f, 0.f);
        if (row0 + r < nrows) v = X[(row0 + r) * 16 + c4];
        *(float4*)&Xs[r][c4 << 2] = v;
    }
    __syncthreads();

    int r  = t >> 2;
    int cb = (t & 3) << 4;
    float4 a0 = make_float4(0.f,0.f,0.f,0.f), a1 = a0, a2 = a0, a3 = a0;
#pragma unroll
    for (int k = 0; k < 64; k++) {
        float xv = Xs[r][k];
        float4 w0 = *(const float4*)&Ws[k][cb +  0];
        float4 w1 = *(const float4*)&Ws[k][cb +  4];
        float4 w2 = *(const float4*)&Ws[k][cb +  8];
        float4 w3 = *(const float4*)&Ws[k][cb + 12];
        fma4(a0, xv, w0); fma4(a1, xv, w1); fma4(a2, xv, w2); fma4(a3, xv, w3);
    }
    int grow = row0 + r;
    if (grow < nrows) {
        if (bias) {
            const float4* b4 = (const float4*)bias;
            int c4 = cb >> 2;
            float4 q;
            q = b4[c4+0]; a0.x+=q.x; a0.y+=q.y; a0.z+=q.z; a0.w+=q.w;
            q = b4[c4+1]; a1.x+=q.x; a1.y+=q.y; a1.z+=q.z; a1.w+=q.w;
            q = b4[c4+2]; a2.x+=q.x; a2.y+=q.y; a2.z+=q.z; a2.w+=q.w;
            q = b4[c4+3]; a3.x+=q.x; a3.y+=q.y; a3.z+=q.z; a3.w+=q.w;
        }
        int o = grow * 16 + (cb >> 2);
        Y[o + 0] = a0; Y[o + 1] = a1; Y[o + 2] = a2; Y[o + 3] = a3;
    }
}

// ---------------- fused: aggregate (CSR gather) + bias + LayerNorm + ReLU + residual --
__global__ __launch_bounds__(256) void k_gather_ln(const float4* __restrict__ hw,
                                                   const float4* __restrict__ hin,
                                                   const float* __restrict__ bconv,
                                                   const float* __restrict__ gam,
                                                   const float* __restrict__ bet,
                                                   float4* __restrict__ out, int N) {
    int t = threadIdx.x;
    int g = t & 15;
    int node = blockIdx.x * 16 + (t >> 4);
    unsigned mask = 0xFFFFu << (t & 16);   // shfl segment mask (safe vs exited groups)
    if (node >= N) return;

    float dv = g_dinv[node];
    float selfn = dv * dv;                 // self-loop norm = 1/deg
    float4 acc = hw[node * 16 + g];
    acc.x *= selfn; acc.y *= selfn; acc.z *= selfn; acc.w *= selfn;

    int e = g_rs[node], eend = g_rs[node + 1];
    if (e < eend) {
        int2 cur = g_csr[e];
        for (; e < eend; ) {
            int2 nxt;
            if (e + 1 < eend) nxt = g_csr[e + 1];
            float w = __int_as_float(cur.y);
            float4 v = hw[cur.x * 16 + g];
            fma4(acc, w, v);
            cur = nxt; ++e;
        }
    }
    // conv bias
    float4 bb = ((const float4*)bconv)[g];
    acc.x += bb.x; acc.y += bb.y; acc.z += bb.z; acc.w += bb.w;

    // LayerNorm over 64 values held by 16 lanes (4 each)
    float s = acc.x + acc.y + acc.z + acc.w;
    s += __shfl_xor_sync(mask, s, 8, 16);
    s += __shfl_xor_sync(mask, s, 4, 16);
    s += __shfl_xor_sync(mask, s, 2, 16);
    s += __shfl_xor_sync(mask, s, 1, 16);
    float m = s * (1.0f / 64.0f);
    float dx = acc.x - m, dy = acc.y - m, dz = acc.z - m, dw = acc.w - m;
    float vs = dx*dx + dy*dy + dz*dz + dw*dw;
    vs += __shfl_xor_sync(mask, vs, 8, 16);
    vs += __shfl_xor_sync(mask, vs, 4, 16);
    vs += __shfl_xor_sync(mask, vs, 2, 16);
    vs += __shfl_xor_sync(mask, vs, 1, 16);
    float rstd = rsqrtf(vs * (1.0f / 64.0f) + 1e-5f);

    float4 gg = ((const float4*)gam)[g];
    float4 be = ((const float4*)bet)[g];
    float4 hi = hin[node * 16 + g];
    float4 o;
    o.x = fmaxf(dx * rstd * gg.x + be.x, 0.f) + hi.x;
    o.y = fmaxf(dy * rstd * gg.y + be.y, 0.f) + hi.y;
    o.z = fmaxf(dz * rstd * gg.z + be.z, 0.f) + hi.z;
    o.w = fmaxf(dw * rstd * gg.w + be.w, 0.f) + hi.w;
    out[node * 16 + g] = o;
}

// ---------------- scoring: s = <hp[u], hp[NU+i]> + bu + bi + mu, clip [1,5] ---------
__global__ __launch_bounds__(256) void k_score(const float4* __restrict__ hp,
                                               const int* __restrict__ users,
                                               const int* __restrict__ items,
                                               const float* __restrict__ bu,
                                               const float* __restrict__ bi,
                                               const float* __restrict__ mu,
                                               float* __restrict__ out, int B, int NU) {
    int t = threadIdx.x;
    int g = t & 15;
    int p = blockIdx.x * 16 + (t >> 4);
    unsigned mask = 0xFFFFu << (t & 16);
    if (p >= B) return;
    int u = users[p], it = items[p];
    float4 a = hp[u * 16 + g];
    float4 c = hp[(NU + it) * 16 + g];
    float s = a.x*c.x + a.y*c.y + a.z*c.z + a.w*c.w;
    s += __shfl_xor_sync(mask, s, 8, 16);
    s += __shfl_xor_sync(mask, s, 4, 16);
    s += __shfl_xor_sync(mask, s, 2, 16);
    s += __shfl_xor_sync(mask, s, 1, 16);
    if (g == 0) {
        float r = s + bu[u] + bi[it] + mu[0];
        out[p] = fminf(fmaxf(r, 1.0f), 5.0f);
    }
}

// ---------------- launch ----------------
extern "C" void kernel_launch(void* const* d_in, const int* in_sizes, int n_in,
                              void* d_out, int out_size) {
    const int*    users = (const int*)d_in[0];
    const int*    items = (const int*)d_in[1];
    const int*    eidx  = (const int*)d_in[2];
    const float*  ew    = (const float*)d_in[3];
    const float4* U     = (const float4*)d_in[4];
    const float4* I     = (const float4*)d_in[5];
    const float*  W0    = (const float*)d_in[6];
    const float*  b0    = (const float*)d_in[7];
    const float*  g0    = (const float*)d_in[8];
    const float*  be0   = (const float*)d_in[9];
    const float*  W1    = (const float*)d_in[10];
    const float*  b1    = (const float*)d_in[11];
    const float*  g1    = (const float*)d_in[12];
    const float*  be1   = (const float*)d_in[13];
    const float*  Wp    = (const float*)d_in[14];
    const float*  bp    = (const float*)d_in[15];
    const float*  bu    = (const float*)d_in[16];
    const float*  bi    = (const float*)d_in[17];
    const float*  mu    = (const float*)d_in[18];
    float* out = (float*)d_out;

    int B  = in_sizes[0];
    int E  = in_sizes[3];
    int NU = in_sizes[16];
    int NI = in_sizes[17];
    int N  = NU + NI;
    const int* esrc = eidx;
    const int* edst = eidx + E;

    // resolve device-scratch addresses (query only; capture-safe, no allocation)
    float4 *p_hw, *p_h, *p_h2;
    cudaGetSymbolAddress((void**)&p_hw, g_hw);
    cudaGetSymbolAddress((void**)&p_h,  g_h);
    cudaGetSymbolAddress((void**)&p_h2, g_h2);

    int nb = (N + 1023) / 1024;

    k_concat<<<(N * 16 + 255) / 256, 256>>>(U, I, NU * 16, N * 16);
    k_init  <<<(N + 255) / 256, 256>>>(N);
    k_deg   <<<2048, 256>>>(edst, ew, E);
    k_dinv  <<<(N + 255) / 256, 256>>>(N);
    k_scan1 <<<nb, 1024>>>(N);
    k_scan2 <<<1, 1024>>>(nb);
    k_scan3 <<<nb, 1024>>>(N, E);
    k_fill  <<<2048, 256>>>(esrc, edst, ew, E);

    // layer 0
    k_gemm      <<<(N + 63) / 64, 256>>>(p_h, W0, nullptr, p_hw, N);
    k_gather_ln <<<(N + 15) / 16, 256>>>(p_hw, p_h, b0, g0, be0, p_h2, N);
    // layer 1
    k_gemm      <<<(N + 63) / 64, 256>>>(p_h2, W1, nullptr, p_hw, N);
    k_gather_ln <<<(N + 15) / 16, 256>>>(p_hw, p_h2, b1, g1, be1, p_h, N);
    // projection
    k_gemm      <<<(N + 63) / 64, 256>>>(p_h, Wp, bp, p_hw, N);
    // scoring
    k_score     <<<(B + 15) / 16, 256>>>(p_hw, users, items, bu, bi, mu, out, B, NU);
}